// round 14
// baseline (speedup 1.0000x reference)
#include <cuda_runtime.h>
#include <cuda_fp16.h>
#include <cstdint>

// Problem constants (fixed shapes)
#define N_NODES 50000
#define T_STEPS 12
#define F_IN    128
#define HEADS   4
#define DDIM    128
#define E_EDGES 800000
#define NEG_SLOPE 0.2f
#define D3      384

#define ND (N_NODES * DDIM)
#define NH (N_NODES * HEADS)

// ---------------- scratch (device globals) ----------------
__device__ __half d_Wg16[DDIM * F_IN];     // [n][k]
__device__ __half d_Wih16[D3 * DDIM];      // [n][k] (native row-major)
__device__ __half d_Whh16[D3 * DDIM];
// per-timestep tensors (hoisted out of the recurrence)
__device__ __half d_hf16[T_STEPS][ND];     // fp16 h features (edge gather)
__device__ float  d_alS[T_STEPS][NH];
__device__ float  d_alD[T_STEPS][NH];
__device__ float  d_denom[T_STEPS][NH];
__device__ float  d_acc[T_STEPS][ND];
__device__ __half d_g16[T_STEPS][ND];      // relu'd GAT output (fp16)
__device__ __half d_gi16[T_STEPS][N_NODES * D3];  // input-gate preacts (fp16)
// recurrence scratch
__device__ __half d_gh16[N_NODES * D3];
__device__ float  d_hstate[ND];            // exact fp32 GRU state
__device__ __half d_h16[ND];               // fp16 copy (GEMM input)

#define ROWH 136                            // halves per smem row (pad)
#define TILEH (128 * ROWH)                  // halves per 128-row tile
#define ATT_SMEM_BYTES   (2 * TILEH * 2 + 2 * 512 * 4)
#define GEMM3_SMEM_BYTES (3 * TILEH * 2)    // A + 2 W stages

__device__ __forceinline__ void mma16816(float* c, const uint32_t* a, const uint32_t* b) {
    asm volatile(
        "mma.sync.aligned.m16n8k16.row.col.f32.f16.f16.f32 "
        "{%0,%1,%2,%3}, {%4,%5,%6,%7}, {%8,%9}, {%0,%1,%2,%3};\n"
        : "+f"(c[0]), "+f"(c[1]), "+f"(c[2]), "+f"(c[3])
        : "r"(a[0]), "r"(a[1]), "r"(a[2]), "r"(a[3]), "r"(b[0]), "r"(b[1]));
}

__device__ __forceinline__ void cp_async16(uint32_t saddr, const void* gptr, int srcsize) {
    asm volatile("cp.async.cg.shared.global [%0], [%1], 16, %2;"
                 :: "r"(saddr), "l"(gptr), "r"(srcsize));
}

__device__ __forceinline__ float tanh_fast(float x) {
    float r;
    asm("tanh.approx.f32 %0, %1;" : "=f"(r) : "f"(x));
    return r;
}

// ---------------- utility kernels ----------------
__global__ void zero_kernel(float* p, __half* q, int n) {
    int i = blockIdx.x * blockDim.x + threadIdx.x;
    if (i < n) { p[i] = 0.0f; q[i] = __float2half(0.0f); }
}

__global__ void conv_w_nk(const float* __restrict__ W, __half* __restrict__ W16, int n) {
    int i = blockIdx.x * blockDim.x + threadIdx.x;
    if (i < n) W16[i] = __float2half_rn(W[i]);
}

// Wg [k][n] row-major -> Wg16 [n][k]
__global__ void conv_wg(const float* __restrict__ Wg, __half* __restrict__ Wg16) {
    int i = blockIdx.x * blockDim.x + threadIdx.x;
    if (i < DDIM * F_IN) {
        int n = i >> 7, k = i & 127;
        Wg16[i] = __float2half_rn(Wg[k * DDIM + n]);
    }
}

// ---------------- batched fp16 GEMM + fused attention epilogue ----------------
// grid (391, T_STEPS): blockIdx.y = timestep.
__global__ __launch_bounds__(256, 2) void gemm_att(
    const float* __restrict__ X, int M,
    const __half* __restrict__ Wt,
    __half* __restrict__ hf16_all,
    const float* __restrict__ a_src, const float* __restrict__ a_dst,
    float* __restrict__ alS_all, float* __restrict__ alD_all,
    float* __restrict__ denom_all, float* __restrict__ acc_all)
{
    extern __shared__ __half smh[];
    __half* As = smh;                 // [128][ROWH]
    __half* Ws = smh + TILEH;         // [128][ROWH]
    float* sS = (float*)(smh + 2 * TILEH);   // [512]
    float* sD = sS + 512;

    const int t = blockIdx.y;
    const float* A = X + (long)t * F_IN;
    const int lda = T_STEPS * F_IN;
    __half* hf16 = hf16_all + (long)t * ND;
    float* alS   = alS_all + (long)t * NH;
    float* alD   = alD_all + (long)t * NH;
    float* denom = denom_all + (long)t * NH;
    float* acc   = acc_all + (long)t * ND;

    const int tid  = threadIdx.x;
    const int lane = tid & 31;
    const int wid  = tid >> 5;
    const int wm   = (wid & 3) * 32;
    const int wn   = (wid >> 2) * 64;
    const int row0 = blockIdx.x * 128;
    const int lq   = lane >> 2;
    const int lr   = lane & 3;

    if (tid < 256) { sS[tid] = 0.f; sS[tid + 256] = 0.f;
                     sD[tid] = 0.f; sD[tid + 256] = 0.f; }

    const uint32_t sW = (uint32_t)__cvta_generic_to_shared(Ws);
    {
        int ra = tid >> 4, c16 = tid & 15;
#pragma unroll
        for (int i = 0; i < 8; i++) {
            int r = ra + i * 16;
            cp_async16(sW + (uint32_t)((r * ROWH + c16 * 8) * 2),
                       &Wt[(long)r * 128 + c16 * 8], 16);
        }
        asm volatile("cp.async.commit_group;");
    }
    {
        int rb = tid >> 5, c4 = tid & 31;
#pragma unroll
        for (int i = 0; i < 16; i++) {
            int r = rb + i * 8;
            int gr = row0 + r;
            float4 v = make_float4(0.f, 0.f, 0.f, 0.f);
            if (gr < M) v = *(const float4*)&A[(long)gr * lda + c4 * 4];
            __half2 h0 = __floats2half2_rn(v.x, v.y);
            __half2 h1 = __floats2half2_rn(v.z, v.w);
            __half2* dp = (__half2*)&As[r * ROWH + c4 * 4];
            dp[0] = h0; dp[1] = h1;
        }
    }
    asm volatile("cp.async.wait_group 0;");
    __syncthreads();

    float cacc[2][8][4];
#pragma unroll
    for (int mf = 0; mf < 2; mf++)
#pragma unroll
        for (int nf = 0; nf < 8; nf++)
#pragma unroll
            for (int q = 0; q < 4; q++) cacc[mf][nf][q] = 0.0f;

#pragma unroll
    for (int ks = 0; ks < 8; ks++) {
        const int kh = ks * 16;
        uint32_t af[2][4];
#pragma unroll
        for (int mf = 0; mf < 2; mf++) {
            int rw = wm + mf * 16 + lq;
            af[mf][0] = *(const uint32_t*)&As[rw * ROWH + kh + 2 * lr];
            af[mf][1] = *(const uint32_t*)&As[(rw + 8) * ROWH + kh + 2 * lr];
            af[mf][2] = *(const uint32_t*)&As[rw * ROWH + kh + 8 + 2 * lr];
            af[mf][3] = *(const uint32_t*)&As[(rw + 8) * ROWH + kh + 8 + 2 * lr];
        }
#pragma unroll
        for (int nf = 0; nf < 8; nf++) {
            int cc = wn + nf * 8 + lq;
            uint32_t bf[2];
            bf[0] = *(const uint32_t*)&Ws[cc * ROWH + kh + 2 * lr];
            bf[1] = *(const uint32_t*)&Ws[cc * ROWH + kh + 8 + 2 * lr];
#pragma unroll
            for (int mf = 0; mf < 2; mf++)
                mma16816(cacc[mf][nf], af[mf], bf);
        }
    }

    // ===== fused attention epilogue =====
    __syncthreads();
    {
        float aSv[8][2], aDv[8][2];
#pragma unroll
        for (int nf = 0; nf < 8; nf++) {
            int cc = wn + nf * 8 + lr * 2;
            aSv[nf][0] = a_src[cc];     aSv[nf][1] = a_src[cc + 1];
            aDv[nf][0] = a_dst[cc];     aDv[nf][1] = a_dst[cc + 1];
        }
#pragma unroll
        for (int mf = 0; mf < 2; mf++) {
#pragma unroll
            for (int half = 0; half < 2; half++) {
                int lrow = wm + mf * 16 + lq + half * 8;
                int h0 = wn >> 5;
                float pS0 = 0.f, pD0 = 0.f, pS1 = 0.f, pD1 = 0.f;
#pragma unroll
                for (int nf = 0; nf < 4; nf++) {
                    float v0 = cacc[mf][nf][half * 2], v1 = cacc[mf][nf][half * 2 + 1];
                    pS0 += v0 * aSv[nf][0] + v1 * aSv[nf][1];
                    pD0 += v0 * aDv[nf][0] + v1 * aDv[nf][1];
                }
#pragma unroll
                for (int nf = 4; nf < 8; nf++) {
                    float v0 = cacc[mf][nf][half * 2], v1 = cacc[mf][nf][half * 2 + 1];
                    pS1 += v0 * aSv[nf][0] + v1 * aSv[nf][1];
                    pD1 += v0 * aDv[nf][0] + v1 * aDv[nf][1];
                }
                atomicAdd(&sS[lrow * HEADS + h0], pS0);
                atomicAdd(&sD[lrow * HEADS + h0], pD0);
                atomicAdd(&sS[lrow * HEADS + h0 + 1], pS1);
                atomicAdd(&sD[lrow * HEADS + h0 + 1], pD1);
            }
        }
    }
    __syncthreads();
    for (int i = tid; i < 128 * HEADS; i += 256) {
        int lrow = i >> 2;
        int gr = row0 + lrow;
        if (gr < M) {
            float sg = sS[i], dg = sD[i];
            float v = sg + dg;
            float e = v > 0.0f ? v : NEG_SLOPE * v;
            float w = __expf(e);
            alS[(long)gr * HEADS + (i & 3)] = sg;
            alD[(long)gr * HEADS + (i & 3)] = dg;
            denom[(long)gr * HEADS + (i & 3)] = w;
            sD[i] = w;
        }
    }
    __syncthreads();
#pragma unroll
    for (int mf = 0; mf < 2; mf++) {
        int lrow = wm + mf * 16 + lq;
#pragma unroll
        for (int nf = 0; nf < 8; nf++) {
            int cc = wn + nf * 8 + lr * 2;
            int head = cc >> 5;
            int r_b = row0 + lrow;
            if (r_b < M) {
                float w = sD[lrow * HEADS + head];
                float2 o = make_float2(cacc[mf][nf][0], cacc[mf][nf][1]);
                *(__half2*)&hf16[(long)r_b * DDIM + cc] = __floats2half2_rn(o.x, o.y);
                *(float2*)&acc[(long)r_b * DDIM + cc] = make_float2(o.x * w, o.y * w);
            }
            if (r_b + 8 < M) {
                float w = sD[(lrow + 8) * HEADS + head];
                float2 o = make_float2(cacc[mf][nf][2], cacc[mf][nf][3]);
                *(__half2*)&hf16[(long)(r_b + 8) * DDIM + cc] = __floats2half2_rn(o.x, o.y);
                *(float2*)&acc[(long)(r_b + 8) * DDIM + cc] = make_float2(o.x * w, o.y * w);
            }
        }
    }
}

// ---------------- per-chunk compute+store for the 3-chunk GEMM ----------------
__device__ __forceinline__ void gemm_chunk(
    const __half* __restrict__ As, const __half* __restrict__ Wsb,
    __half* __restrict__ C, const float* __restrict__ bias, int c0,
    int M, int row0, int wm, int wn, int lq, int lr)
{
    float cacc[2][8][4];
#pragma unroll
    for (int mf = 0; mf < 2; mf++)
#pragma unroll
        for (int nf = 0; nf < 8; nf++)
#pragma unroll
            for (int q = 0; q < 4; q++) cacc[mf][nf][q] = 0.0f;

#pragma unroll
    for (int ks = 0; ks < 8; ks++) {
        const int kh = ks * 16;
        uint32_t af[2][4];
#pragma unroll
        for (int mf = 0; mf < 2; mf++) {
            int rw = wm + mf * 16 + lq;
            af[mf][0] = *(const uint32_t*)&As[rw * ROWH + kh + 2 * lr];
            af[mf][1] = *(const uint32_t*)&As[(rw + 8) * ROWH + kh + 2 * lr];
            af[mf][2] = *(const uint32_t*)&As[rw * ROWH + kh + 8 + 2 * lr];
            af[mf][3] = *(const uint32_t*)&As[(rw + 8) * ROWH + kh + 8 + 2 * lr];
        }
#pragma unroll
        for (int nf = 0; nf < 8; nf++) {
            int cc = wn + nf * 8 + lq;
            uint32_t bf[2];
            bf[0] = *(const uint32_t*)&Wsb[cc * ROWH + kh + 2 * lr];
            bf[1] = *(const uint32_t*)&Wsb[cc * ROWH + kh + 8 + 2 * lr];
#pragma unroll
            for (int mf = 0; mf < 2; mf++)
                mma16816(cacc[mf][nf], af[mf], bf);
        }
    }

#pragma unroll
    for (int mf = 0; mf < 2; mf++) {
        int r_b = row0 + wm + mf * 16 + lq;
#pragma unroll
        for (int nf = 0; nf < 8; nf++) {
            int cc = c0 + wn + nf * 8 + lr * 2;
            float b0 = bias[cc];
            float b1 = bias[cc + 1];
            if (r_b < M)
                *(__half2*)&C[(long)r_b * D3 + cc] =
                    __floats2half2_rn(cacc[mf][nf][0] + b0, cacc[mf][nf][1] + b1);
            if (r_b + 8 < M)
                *(__half2*)&C[(long)(r_b + 8) * D3 + cc] =
                    __floats2half2_rn(cacc[mf][nf][2] + b0, cacc[mf][nf][3] + b1);
        }
    }
}

// ---------------- 3-chunk fp16 GEMM: A loaded ONCE, W double-buffered ----------------
// grid (GX, 1, NB): C[z] = A[z] @ W^T + bias over all 384 cols.
__global__ __launch_bounds__(256, 2) void gemm_f16_c3(
    const __half* __restrict__ Abase, long Astr, int M,
    const __half* __restrict__ Wt,
    const float* __restrict__ bias,
    __half* __restrict__ Cbase, long Cstr)
{
    extern __shared__ __half smh[];
    __half* As  = smh;
    __half* Ws0 = smh + TILEH;
    __half* Ws1 = smh + 2 * TILEH;

    const __half* A = Abase + (long)blockIdx.z * Astr;
    __half* C = Cbase + (long)blockIdx.z * Cstr;

    const int tid  = threadIdx.x;
    const int lane = tid & 31;
    const int wid  = tid >> 5;
    const int wm   = (wid & 3) * 32;
    const int wn   = (wid >> 2) * 64;
    const int row0 = blockIdx.x * 128;
    const int lq   = lane >> 2;
    const int lr   = lane & 3;

    const uint32_t sA  = (uint32_t)__cvta_generic_to_shared(As);
    const uint32_t sW0 = (uint32_t)__cvta_generic_to_shared(Ws0);
    const uint32_t sW1 = (uint32_t)__cvta_generic_to_shared(Ws1);

    const int ra = tid >> 4, c16 = tid & 15;

#define LOAD_W(sdst_, chunk_)                                                   \
    _Pragma("unroll")                                                           \
    for (int i = 0; i < 8; i++) {                                               \
        int r_ = ra + i * 16;                                                   \
        cp_async16((sdst_) + (uint32_t)((r_ * ROWH + c16 * 8) * 2),             \
                   &Wt[(long)((chunk_) * 128 + r_) * 128 + c16 * 8], 16);       \
    }

    // stage: A + W0 (group 0), W1 (group 1)
#pragma unroll
    for (int i = 0; i < 8; i++) {
        int r = ra + i * 16;
        int gr = row0 + r;
        const __half* gp = &A[(long)(gr < M ? gr : 0) * 128 + c16 * 8];
        cp_async16(sA + (uint32_t)((r * ROWH + c16 * 8) * 2), gp, gr < M ? 16 : 0);
    }
    LOAD_W(sW0, 0);
    asm volatile("cp.async.commit_group;");
    LOAD_W(sW1, 1);
    asm volatile("cp.async.commit_group;");

    // chunk 0
    asm volatile("cp.async.wait_group 1;");
    __syncthreads();
    gemm_chunk(As, Ws0, C, bias, 0, M, row0, wm, wn, lq, lr);
    __syncthreads();                      // all reads of Ws0 done
    LOAD_W(sW0, 2);                       // W2 into buffer 0
    asm volatile("cp.async.commit_group;");

    // chunk 1
    asm volatile("cp.async.wait_group 1;");   // W1 complete
    __syncthreads();
    gemm_chunk(As, Ws1, C, bias, 128, M, row0, wm, wn, lq, lr);

    // chunk 2
    asm volatile("cp.async.wait_group 0;");   // W2 complete
    __syncthreads();
    gemm_chunk(As, Ws0, C, bias, 256, M, row0, wm, wn, lq, lr);
#undef LOAD_W
}

// ---------------- batched edge pass: grid.y = timestep ----------------
__device__ __forceinline__ void red_add_v4(float* addr, float a, float b, float c, float d) {
    asm volatile("red.global.add.v4.f32 [%0], {%1,%2,%3,%4};"
                 :: "l"(addr), "f"(a), "f"(b), "f"(c), "f"(d) : "memory");
}

__global__ __launch_bounds__(256) void edge_kernel(
    const int* __restrict__ ei,
    const float* __restrict__ alS_all, const float* __restrict__ alD_all,
    const __half* __restrict__ hf16_all,
    float* __restrict__ denom_all, float* __restrict__ acc_all)
{
    const int t = blockIdx.y;
    const int* src_arr = ei + (long)t * 2 * E_EDGES;
    const int* dst_arr = src_arr + E_EDGES;
    const float* alS = alS_all + (long)t * NH;
    const float* alD = alD_all + (long)t * NH;
    const __half* hf16 = hf16_all + (long)t * ND;
    float* denom = denom_all + (long)t * NH;
    float* acc   = acc_all + (long)t * ND;

    long gw = (long)blockIdx.x * (blockDim.x >> 5) + (threadIdx.x >> 5);
    if (gw >= E_EDGES) return;
    int lane = threadIdx.x & 31;
    int head = lane >> 3;

    int s = src_arr[gw];
    int d = dst_arr[gw];

    float v = alS[s * HEADS + head] + alD[d * HEADS + head];
    float e = v > 0.0f ? v : NEG_SLOPE * v;
    float w = __expf(e);

    if ((lane & 7) == 0) atomicAdd(&denom[d * HEADS + head], w);

    uint2 hv = ((const uint2*)hf16)[s * 32 + lane];
    float2 f0 = __half22float2(*(__half2*)&hv.x);
    float2 f1 = __half22float2(*(__half2*)&hv.y);
    red_add_v4(&acc[d * DDIM + lane * 4], w * f0.x, w * f0.y, w * f1.x, w * f1.y);
}

// ---------------- batched finalize: grid.y = timestep ----------------
__global__ void finalize_gat(
    const float* __restrict__ acc_all, const float* __restrict__ denom_all,
    const float* __restrict__ bg, __half* __restrict__ g16_all)
{
    const int t = blockIdx.y;
    const float* acc = acc_all + (long)t * ND;
    const float* denom = denom_all + (long)t * NH;
    __half* g16 = g16_all + (long)t * ND;

    int idx = blockIdx.x * blockDim.x + threadIdx.x;   // over N*32 float4s
    if (idx >= N_NODES * 32) return;
    int n = idx >> 5;
    int c4 = idx & 31;
    int head = c4 >> 3;
    float inv = 1.0f / (denom[n * HEADS + head] + 1e-16f);
    float4 a = ((const float4*)acc)[idx];
    float4 b = ((const float4*)bg)[c4];
    __half2 p0 = __floats2half2_rn(fmaxf(a.x * inv + b.x, 0.0f),
                                   fmaxf(a.y * inv + b.y, 0.0f));
    __half2 p1 = __floats2half2_rn(fmaxf(a.z * inv + b.z, 0.0f),
                                   fmaxf(a.w * inv + b.w, 0.0f));
    ((__half2*)g16)[idx * 2] = p0;
    ((__half2*)g16)[idx * 2 + 1] = p1;
}

// ---------------- GRU gates: fp16 gi/gh inputs ----------------
__global__ void gru_gates(
    const __half* __restrict__ gi, const __half* __restrict__ gh,
    float* __restrict__ h, __half* __restrict__ h16)
{
    int idx = blockIdx.x * blockDim.x + threadIdx.x;   // over N*32 float4 groups
    if (idx >= N_NODES * 32) return;
    int n = idx >> 5;
    long baseh = (long)n * D3 + (idx & 31) * 4;        // half index
    uint2 irv = *(const uint2*)&gi[baseh];
    uint2 hrv = *(const uint2*)&gh[baseh];
    uint2 izv = *(const uint2*)&gi[baseh + 128];
    uint2 hzv = *(const uint2*)&gh[baseh + 128];
    uint2 inv = *(const uint2*)&gi[baseh + 256];
    uint2 hnv = *(const uint2*)&gh[baseh + 256];
    float4 hv = ((const float4*)h)[idx];
    float ir[4], hr[4], iz[4], hz[4], in_[4], hn[4];
    {
        float2 a, b;
        a = __half22float2(*(__half2*)&irv.x); b = __half22float2(*(__half2*)&irv.y);
        ir[0]=a.x; ir[1]=a.y; ir[2]=b.x; ir[3]=b.y;
        a = __half22float2(*(__half2*)&hrv.x); b = __half22float2(*(__half2*)&hrv.y);
        hr[0]=a.x; hr[1]=a.y; hr[2]=b.x; hr[3]=b.y;
        a = __half22float2(*(__half2*)&izv.x); b = __half22float2(*(__half2*)&izv.y);
        iz[0]=a.x; iz[1]=a.y; iz[2]=b.x; iz[3]=b.y;
        a = __half22float2(*(__half2*)&hzv.x); b = __half22float2(*(__half2*)&hzv.y);
        hz[0]=a.x; hz[1]=a.y; hz[2]=b.x; hz[3]=b.y;
        a = __half22float2(*(__half2*)&inv.x); b = __half22float2(*(__half2*)&inv.y);
        in_[0]=a.x; in_[1]=a.y; in_[2]=b.x; in_[3]=b.y;
        a = __half22float2(*(__half2*)&hnv.x); b = __half22float2(*(__half2*)&hnv.y);
        hn[0]=a.x; hn[1]=a.y; hn[2]=b.x; hn[3]=b.y;
    }
    float4 ho;
#pragma unroll
    for (int q = 0; q < 4; q++) {
        float r = 1.0f / (1.0f + __expf(-(ir[q] + hr[q])));
        float z = 1.0f / (1.0f + __expf(-(iz[q] + hz[q])));
        float nn = tanh_fast(in_[q] + r * hn[q]);
        (&ho.x)[q] = (1.0f - z) * nn + z * (&hv.x)[q];
    }
    ((float4*)h)[idx] = ho;
    ((__half2*)h16)[idx * 2]     = __floats2half2_rn(ho.x, ho.y);
    ((__half2*)h16)[idx * 2 + 1] = __floats2half2_rn(ho.z, ho.w);
}

// ---------------- final linear ----------------
__global__ __launch_bounds__(256) void final_linear(
    const float* __restrict__ h, const float* __restrict__ Wl,
    const float* __restrict__ bl, float* __restrict__ out)
{
    int warp = (blockIdx.x * blockDim.x + threadIdx.x) >> 5;
    int lane = threadIdx.x & 31;
    if (warp >= N_NODES) return;
    float4 hv = ((const float4*)h)[warp * 32 + lane];
    float4 wv = ((const float4*)Wl)[lane];
    float s = hv.x * wv.x + hv.y * wv.y + hv.z * wv.z + hv.w * wv.w;
#pragma unroll
    for (int off = 16; off > 0; off >>= 1)
        s += __shfl_down_sync(0xffffffffu, s, off);
    if (lane == 0) out[warp] = s + bl[0];
}

// ---------------- launcher ----------------
extern "C" void kernel_launch(void* const* d_in, const int* in_sizes, int n_in,
                              void* d_out, int out_size)
{
    const float* x   = (const float*)d_in[0];
    const int*   ei  = (const int*)d_in[1];
    const float* Wg  = (const float*)d_in[2];
    const float* as  = (const float*)d_in[3];
    const float* ad  = (const float*)d_in[4];
    const float* bg  = (const float*)d_in[5];
    const float* Wih = (const float*)d_in[6];
    const float* Whh = (const float*)d_in[7];
    const float* bih = (const float*)d_in[8];
    const float* bhh = (const float*)d_in[9];
    const float* Wl  = (const float*)d_in[10];
    const float* bl  = (const float*)d_in[11];
    float* out = (float*)d_out;

    float *alS, *alD, *denom, *acc, *hstate;
    __half *Wg16, *Wih16, *Whh16, *hf16, *g16, *gi16, *gh16, *h16;
    cudaGetSymbolAddress((void**)&alS,    d_alS);
    cudaGetSymbolAddress((void**)&alD,    d_alD);
    cudaGetSymbolAddress((void**)&denom,  d_denom);
    cudaGetSymbolAddress((void**)&acc,    d_acc);
    cudaGetSymbolAddress((void**)&hstate, d_hstate);
    cudaGetSymbolAddress((void**)&Wg16,   d_Wg16);
    cudaGetSymbolAddress((void**)&Wih16,  d_Wih16);
    cudaGetSymbolAddress((void**)&Whh16,  d_Whh16);
    cudaGetSymbolAddress((void**)&hf16,   d_hf16);
    cudaGetSymbolAddress((void**)&g16,    d_g16);
    cudaGetSymbolAddress((void**)&gi16,   d_gi16);
    cudaGetSymbolAddress((void**)&gh16,   d_gh16);
    cudaGetSymbolAddress((void**)&h16,    d_h16);

    cudaFuncSetAttribute(gemm_att,
                         cudaFuncAttributeMaxDynamicSharedMemorySize, ATT_SMEM_BYTES);
    cudaFuncSetAttribute(gemm_f16_c3,
                         cudaFuncAttributeMaxDynamicSharedMemorySize, GEMM3_SMEM_BYTES);

    const int GX = (N_NODES + 127) / 128;   // 391

    // prologue: zero state, convert weights to fp16
    zero_kernel<<<(ND + 255) / 256, 256>>>(hstate, h16, ND);
    conv_wg<<<(DDIM * F_IN + 255) / 256, 256>>>(Wg, Wg16);
    conv_w_nk<<<(D3 * DDIM + 255) / 256, 256>>>(Wih, Wih16, D3 * DDIM);
    conv_w_nk<<<(D3 * DDIM + 255) / 256, 256>>>(Whh, Whh16, D3 * DDIM);

    // ===== hoisted, batched non-recurrent pipeline =====
    gemm_att<<<dim3(GX, T_STEPS), 256, ATT_SMEM_BYTES>>>(
        x, N_NODES, Wg16, hf16, as, ad, alS, alD, denom, acc);
    edge_kernel<<<dim3((E_EDGES * 32 + 255) / 256, T_STEPS), 256>>>(
        ei, alS, alD, hf16, denom, acc);
    finalize_gat<<<dim3((N_NODES * 32 + 255) / 256, T_STEPS), 256>>>(acc, denom, bg, g16);
    gemm_f16_c3<<<dim3(GX, 1, T_STEPS), 256, GEMM3_SMEM_BYTES>>>(
        g16, (long)ND, N_NODES, Wih16, bih, gi16, (long)N_NODES * D3);

    // ===== recurrence: only gh + gates =====
    for (int t = 0; t < T_STEPS; t++) {
        gemm_f16_c3<<<dim3(GX, 1, 1), 256, GEMM3_SMEM_BYTES>>>(
            h16, 0L, N_NODES, Whh16, bhh, gh16, 0L);
        gru_gates<<<(N_NODES * 32 + 255) / 256, 256>>>(
            gi16 + (long)t * N_NODES * D3, gh16, hstate, h16);
    }

    final_linear<<<(N_NODES * 32 + 255) / 256, 256>>>(hstate, Wl, bl, out);
}

// round 15
// speedup vs baseline: 1.4613x; 1.4613x over previous
#include <cuda_runtime.h>
#include <cuda_fp16.h>
#include <cstdint>

// Problem constants (fixed shapes)
#define N_NODES 50000
#define T_STEPS 12
#define F_IN    128
#define HEADS   4
#define DDIM    128
#define E_EDGES 800000
#define NEG_SLOPE 0.2f
#define D3      384

#define ND (N_NODES * DDIM)
#define NH (N_NODES * HEADS)

// ---------------- scratch (device globals) ----------------
__device__ __half d_Wg16[DDIM * F_IN];     // [n][k]
__device__ __half d_Wih16[D3 * DDIM];      // [n][k]
__device__ __half d_Whh16[D3 * DDIM];
// per-timestep tensors (hoisted out of the recurrence)
__device__ __half d_hf16[T_STEPS][ND];     // fp16 h features
__device__ float  d_alS[T_STEPS][NH];
__device__ float  d_alD[T_STEPS][NH];
__device__ __half d_g16[T_STEPS][ND];      // relu'd GAT output (fp16)
__device__ __half d_gi16[T_STEPS][N_NODES * D3];
// CSR scratch
__device__ int    d_deg[T_STEPS][N_NODES];
__device__ int    d_off[T_STEPS][N_NODES];
__device__ int    d_cur[T_STEPS][N_NODES];
__device__ int    d_srclist[T_STEPS][E_EDGES];
// recurrence scratch
__device__ __half d_gh16[N_NODES * D3];
__device__ float  d_hstate[ND];
__device__ __half d_h16[ND];

#define ROWH 136
#define TILEH (128 * ROWH)
#define ATT_SMEM_BYTES   (2 * TILEH * 2 + 2 * 512 * 4)
#define GEMM3_SMEM_BYTES (3 * TILEH * 2)

__device__ __forceinline__ void mma16816(float* c, const uint32_t* a, const uint32_t* b) {
    asm volatile(
        "mma.sync.aligned.m16n8k16.row.col.f32.f16.f16.f32 "
        "{%0,%1,%2,%3}, {%4,%5,%6,%7}, {%8,%9}, {%0,%1,%2,%3};\n"
        : "+f"(c[0]), "+f"(c[1]), "+f"(c[2]), "+f"(c[3])
        : "r"(a[0]), "r"(a[1]), "r"(a[2]), "r"(a[3]), "r"(b[0]), "r"(b[1]));
}

__device__ __forceinline__ void cp_async16(uint32_t saddr, const void* gptr, int srcsize) {
    asm volatile("cp.async.cg.shared.global [%0], [%1], 16, %2;"
                 :: "r"(saddr), "l"(gptr), "r"(srcsize));
}

__device__ __forceinline__ float tanh_fast(float x) {
    float r;
    asm("tanh.approx.f32 %0, %1;" : "=f"(r) : "f"(x));
    return r;
}

// ---------------- utility kernels ----------------
__global__ void zero_kernel(float* p, __half* q, int n) {
    int i = blockIdx.x * blockDim.x + threadIdx.x;
    if (i < n) { p[i] = 0.0f; q[i] = __float2half(0.0f); }
}

__global__ void zero_int(int* p, int n) {
    int i = blockIdx.x * blockDim.x + threadIdx.x;
    if (i < n) p[i] = 0;
}

__global__ void conv_w_nk(const float* __restrict__ W, __half* __restrict__ W16, int n) {
    int i = blockIdx.x * blockDim.x + threadIdx.x;
    if (i < n) W16[i] = __float2half_rn(W[i]);
}

__global__ void conv_wg(const float* __restrict__ Wg, __half* __restrict__ Wg16) {
    int i = blockIdx.x * blockDim.x + threadIdx.x;
    if (i < DDIM * F_IN) {
        int n = i >> 7, k = i & 127;
        Wg16[i] = __float2half_rn(Wg[k * DDIM + n]);
    }
}

// ---------------- CSR build ----------------
__global__ void count_kernel(const int* __restrict__ ei, int* __restrict__ deg) {
    const int t = blockIdx.y;
    long i = (long)blockIdx.x * blockDim.x + threadIdx.x;
    if (i >= E_EDGES) return;
    int d = ei[(long)t * 2 * E_EDGES + E_EDGES + i];
    atomicAdd(&deg[t * N_NODES + d], 1);
}

// one block (1024 thr) per timestep: exclusive scan of deg -> off, cur
__global__ __launch_bounds__(1024) void scan_kernel(
    const int* __restrict__ deg, int* __restrict__ off, int* __restrict__ cur)
{
    const int t = blockIdx.x;
    const int base = t * N_NODES;
    const int CH = (N_NODES + 1023) / 1024;   // 49
    const int tid = threadIdx.x;
    const int start = tid * CH;

    int sum = 0;
    for (int i = 0; i < CH; i++) {
        int idx = start + i;
        if (idx < N_NODES) sum += deg[base + idx];
    }
    __shared__ int part[1024];
    part[tid] = sum;
    __syncthreads();
    for (int d = 1; d < 1024; d <<= 1) {
        int v = 0;
        if (tid >= d) v = part[tid - d];
        __syncthreads();
        if (tid >= d) part[tid] += v;
        __syncthreads();
    }
    int run = (tid == 0) ? 0 : part[tid - 1];
    for (int i = 0; i < CH; i++) {
        int idx = start + i;
        if (idx < N_NODES) {
            off[base + idx] = run;
            cur[base + idx] = run;
            run += deg[base + idx];
        }
    }
}

__global__ void scatter_kernel(const int* __restrict__ ei,
                               int* __restrict__ cur, int* __restrict__ srclist) {
    const int t = blockIdx.y;
    long i = (long)blockIdx.x * blockDim.x + threadIdx.x;
    if (i >= E_EDGES) return;
    int s = ei[(long)t * 2 * E_EDGES + i];
    int d = ei[(long)t * 2 * E_EDGES + E_EDGES + i];
    int pos = atomicAdd(&cur[t * N_NODES + d], 1);
    srclist[(long)t * E_EDGES + pos] = s;
}

// ---------------- batched fp16 GEMM + attention-logit epilogue ----------------
// Writes hf16 (fp16 h) and alS/alD only.
__global__ __launch_bounds__(256, 2) void gemm_att(
    const float* __restrict__ X, int M,
    const __half* __restrict__ Wt,
    __half* __restrict__ hf16_all,
    const float* __restrict__ a_src, const float* __restrict__ a_dst,
    float* __restrict__ alS_all, float* __restrict__ alD_all)
{
    extern __shared__ __half smh[];
    __half* As = smh;                 // [128][ROWH]
    __half* Ws = smh + TILEH;         // [128][ROWH]
    float* sS = (float*)(smh + 2 * TILEH);   // [512]
    float* sD = sS + 512;

    const int t = blockIdx.y;
    const float* A = X + (long)t * F_IN;
    const int lda = T_STEPS * F_IN;
    __half* hf16 = hf16_all + (long)t * ND;
    float* alS   = alS_all + (long)t * NH;
    float* alD   = alD_all + (long)t * NH;

    const int tid  = threadIdx.x;
    const int lane = tid & 31;
    const int wid  = tid >> 5;
    const int wm   = (wid & 3) * 32;
    const int wn   = (wid >> 2) * 64;
    const int row0 = blockIdx.x * 128;
    const int lq   = lane >> 2;
    const int lr   = lane & 3;

    if (tid < 256) { sS[tid] = 0.f; sS[tid + 256] = 0.f;
                     sD[tid] = 0.f; sD[tid + 256] = 0.f; }

    const uint32_t sW = (uint32_t)__cvta_generic_to_shared(Ws);
    {
        int ra = tid >> 4, c16 = tid & 15;
#pragma unroll
        for (int i = 0; i < 8; i++) {
            int r = ra + i * 16;
            cp_async16(sW + (uint32_t)((r * ROWH + c16 * 8) * 2),
                       &Wt[(long)r * 128 + c16 * 8], 16);
        }
        asm volatile("cp.async.commit_group;");
    }
    {
        int rb = tid >> 5, c4 = tid & 31;
#pragma unroll
        for (int i = 0; i < 16; i++) {
            int r = rb + i * 8;
            int gr = row0 + r;
            float4 v = make_float4(0.f, 0.f, 0.f, 0.f);
            if (gr < M) v = *(const float4*)&A[(long)gr * lda + c4 * 4];
            __half2 h0 = __floats2half2_rn(v.x, v.y);
            __half2 h1 = __floats2half2_rn(v.z, v.w);
            __half2* dp = (__half2*)&As[r * ROWH + c4 * 4];
            dp[0] = h0; dp[1] = h1;
        }
    }
    asm volatile("cp.async.wait_group 0;");
    __syncthreads();

    float cacc[2][8][4];
#pragma unroll
    for (int mf = 0; mf < 2; mf++)
#pragma unroll
        for (int nf = 0; nf < 8; nf++)
#pragma unroll
            for (int q = 0; q < 4; q++) cacc[mf][nf][q] = 0.0f;

#pragma unroll
    for (int ks = 0; ks < 8; ks++) {
        const int kh = ks * 16;
        uint32_t af[2][4];
#pragma unroll
        for (int mf = 0; mf < 2; mf++) {
            int rw = wm + mf * 16 + lq;
            af[mf][0] = *(const uint32_t*)&As[rw * ROWH + kh + 2 * lr];
            af[mf][1] = *(const uint32_t*)&As[(rw + 8) * ROWH + kh + 2 * lr];
            af[mf][2] = *(const uint32_t*)&As[rw * ROWH + kh + 8 + 2 * lr];
            af[mf][3] = *(const uint32_t*)&As[(rw + 8) * ROWH + kh + 8 + 2 * lr];
        }
#pragma unroll
        for (int nf = 0; nf < 8; nf++) {
            int cc = wn + nf * 8 + lq;
            uint32_t bf[2];
            bf[0] = *(const uint32_t*)&Ws[cc * ROWH + kh + 2 * lr];
            bf[1] = *(const uint32_t*)&Ws[cc * ROWH + kh + 8 + 2 * lr];
#pragma unroll
            for (int mf = 0; mf < 2; mf++)
                mma16816(cacc[mf][nf], af[mf], bf);
        }
    }

    // ===== attention-logit epilogue (alS/alD only) + hf16 store =====
    __syncthreads();
    {
        float aSv[8][2], aDv[8][2];
#pragma unroll
        for (int nf = 0; nf < 8; nf++) {
            int cc = wn + nf * 8 + lr * 2;
            aSv[nf][0] = a_src[cc];     aSv[nf][1] = a_src[cc + 1];
            aDv[nf][0] = a_dst[cc];     aDv[nf][1] = a_dst[cc + 1];
        }
#pragma unroll
        for (int mf = 0; mf < 2; mf++) {
#pragma unroll
            for (int half = 0; half < 2; half++) {
                int lrow = wm + mf * 16 + lq + half * 8;
                int h0 = wn >> 5;
                float pS0 = 0.f, pD0 = 0.f, pS1 = 0.f, pD1 = 0.f;
#pragma unroll
                for (int nf = 0; nf < 4; nf++) {
                    float v0 = cacc[mf][nf][half * 2], v1 = cacc[mf][nf][half * 2 + 1];
                    pS0 += v0 * aSv[nf][0] + v1 * aSv[nf][1];
                    pD0 += v0 * aDv[nf][0] + v1 * aDv[nf][1];
                }
#pragma unroll
                for (int nf = 4; nf < 8; nf++) {
                    float v0 = cacc[mf][nf][half * 2], v1 = cacc[mf][nf][half * 2 + 1];
                    pS1 += v0 * aSv[nf][0] + v1 * aSv[nf][1];
                    pD1 += v0 * aDv[nf][0] + v1 * aDv[nf][1];
                }
                atomicAdd(&sS[lrow * HEADS + h0], pS0);
                atomicAdd(&sD[lrow * HEADS + h0], pD0);
                atomicAdd(&sS[lrow * HEADS + h0 + 1], pS1);
                atomicAdd(&sD[lrow * HEADS + h0 + 1], pD1);
            }
        }
    }
    __syncthreads();
    for (int i = tid; i < 128 * HEADS; i += 256) {
        int lrow = i >> 2;
        int gr = row0 + lrow;
        if (gr < M) {
            alS[(long)gr * HEADS + (i & 3)] = sS[i];
            alD[(long)gr * HEADS + (i & 3)] = sD[i];
        }
    }
#pragma unroll
    for (int mf = 0; mf < 2; mf++) {
        int lrow = wm + mf * 16 + lq;
#pragma unroll
        for (int nf = 0; nf < 8; nf++) {
            int cc = wn + nf * 8 + lr * 2;
            int r_b = row0 + lrow;
            if (r_b < M)
                *(__half2*)&hf16[(long)r_b * DDIM + cc] =
                    __floats2half2_rn(cacc[mf][nf][0], cacc[mf][nf][1]);
            if (r_b + 8 < M)
                *(__half2*)&hf16[(long)(r_b + 8) * DDIM + cc] =
                    __floats2half2_rn(cacc[mf][nf][2], cacc[mf][nf][3]);
        }
    }
}

// ---------------- CSR gather: one warp per (node, t); fused finalize ----------------
// acc/denom in registers; writes g16 = fp16(relu(acc/denom + bg)).
__global__ __launch_bounds__(256) void gather_kernel(
    const int* __restrict__ deg, const int* __restrict__ off,
    const int* __restrict__ srclist,
    const float* __restrict__ alS_all, const float* __restrict__ alD_all,
    const __half* __restrict__ hf16_all,
    const float* __restrict__ bg, __half* __restrict__ g16_all)
{
    const int t = blockIdx.y;
    int n = (blockIdx.x * blockDim.x + threadIdx.x) >> 5;
    if (n >= N_NODES) return;
    const int lane = threadIdx.x & 31;
    const int head = lane >> 3;

    const float* alS = alS_all + (long)t * NH;
    const float* alD = alD_all + (long)t * NH;
    const __half* hf = hf16_all + (long)t * ND;
    __half* g16 = g16_all + (long)t * ND;

    const float alDn = alD[n * HEADS + head];

    // self loop
    float v = alS[n * HEADS + head] + alDn;
    float e = v > 0.0f ? v : NEG_SLOPE * v;
    float w = __expf(e);
    uint2 hv = ((const uint2*)hf)[n * 32 + lane];
    float2 f0 = __half22float2(*(__half2*)&hv.x);
    float2 f1 = __half22float2(*(__half2*)&hv.y);
    float a0 = w * f0.x, a1 = w * f0.y, a2 = w * f1.x, a3 = w * f1.y;
    float dsum = w;   // identical across the 8 lanes of each head group

    const int st = off[t * N_NODES + n];
    const int cnt = deg[t * N_NODES + n];
    const int* sl = srclist + (long)t * E_EDGES + st;
    for (int i = 0; i < cnt; i++) {
        int s = sl[i];
        float vv = alS[s * HEADS + head] + alDn;
        float ee = vv > 0.0f ? vv : NEG_SLOPE * vv;
        float ww = __expf(ee);
        uint2 h2 = ((const uint2*)hf)[s * 32 + lane];
        float2 g0 = __half22float2(*(__half2*)&h2.x);
        float2 g1 = __half22float2(*(__half2*)&h2.y);
        a0 += ww * g0.x; a1 += ww * g0.y; a2 += ww * g1.x; a3 += ww * g1.y;
        dsum += ww;
    }

    float inv = 1.0f / (dsum + 1e-16f);
    float4 b = ((const float4*)bg)[lane];
    __half2 p0 = __floats2half2_rn(fmaxf(a0 * inv + b.x, 0.0f),
                                   fmaxf(a1 * inv + b.y, 0.0f));
    __half2 p1 = __floats2half2_rn(fmaxf(a2 * inv + b.z, 0.0f),
                                   fmaxf(a3 * inv + b.w, 0.0f));
    __half2* dst = (__half2*)&g16[(long)n * DDIM + lane * 4];
    dst[0] = p0; dst[1] = p1;
}

// ---------------- per-chunk compute+store for the 3-chunk GEMM ----------------
__device__ __forceinline__ void gemm_chunk(
    const __half* __restrict__ As, const __half* __restrict__ Wsb,
    __half* __restrict__ C, const float* __restrict__ bias, int c0,
    int M, int row0, int wm, int wn, int lq, int lr)
{
    float cacc[2][8][4];
#pragma unroll
    for (int mf = 0; mf < 2; mf++)
#pragma unroll
        for (int nf = 0; nf < 8; nf++)
#pragma unroll
            for (int q = 0; q < 4; q++) cacc[mf][nf][q] = 0.0f;

#pragma unroll
    for (int ks = 0; ks < 8; ks++) {
        const int kh = ks * 16;
        uint32_t af[2][4];
#pragma unroll
        for (int mf = 0; mf < 2; mf++) {
            int rw = wm + mf * 16 + lq;
            af[mf][0] = *(const uint32_t*)&As[rw * ROWH + kh + 2 * lr];
            af[mf][1] = *(const uint32_t*)&As[(rw + 8) * ROWH + kh + 2 * lr];
            af[mf][2] = *(const uint32_t*)&As[rw * ROWH + kh + 8 + 2 * lr];
            af[mf][3] = *(const uint32_t*)&As[(rw + 8) * ROWH + kh + 8 + 2 * lr];
        }
#pragma unroll
        for (int nf = 0; nf < 8; nf++) {
            int cc = wn + nf * 8 + lq;
            uint32_t bf[2];
            bf[0] = *(const uint32_t*)&Wsb[cc * ROWH + kh + 2 * lr];
            bf[1] = *(const uint32_t*)&Wsb[cc * ROWH + kh + 8 + 2 * lr];
#pragma unroll
            for (int mf = 0; mf < 2; mf++)
                mma16816(cacc[mf][nf], af[mf], bf);
        }
    }

#pragma unroll
    for (int mf = 0; mf < 2; mf++) {
        int r_b = row0 + wm + mf * 16 + lq;
#pragma unroll
        for (int nf = 0; nf < 8; nf++) {
            int cc = c0 + wn + nf * 8 + lr * 2;
            float b0 = bias[cc];
            float b1 = bias[cc + 1];
            if (r_b < M)
                *(__half2*)&C[(long)r_b * D3 + cc] =
                    __floats2half2_rn(cacc[mf][nf][0] + b0, cacc[mf][nf][1] + b1);
            if (r_b + 8 < M)
                *(__half2*)&C[(long)(r_b + 8) * D3 + cc] =
                    __floats2half2_rn(cacc[mf][nf][2] + b0, cacc[mf][nf][3] + b1);
        }
    }
}

// ---------------- 3-chunk fp16 GEMM ----------------
__global__ __launch_bounds__(256, 2) void gemm_f16_c3(
    const __half* __restrict__ Abase, long Astr, int M,
    const __half* __restrict__ Wt,
    const float* __restrict__ bias,
    __half* __restrict__ Cbase, long Cstr)
{
    extern __shared__ __half smh[];
    __half* As  = smh;
    __half* Ws0 = smh + TILEH;
    __half* Ws1 = smh + 2 * TILEH;

    const __half* A = Abase + (long)blockIdx.z * Astr;
    __half* C = Cbase + (long)blockIdx.z * Cstr;

    const int tid  = threadIdx.x;
    const int lane = tid & 31;
    const int wid  = tid >> 5;
    const int wm   = (wid & 3) * 32;
    const int wn   = (wid >> 2) * 64;
    const int row0 = blockIdx.x * 128;
    const int lq   = lane >> 2;
    const int lr   = lane & 3;

    const uint32_t sA  = (uint32_t)__cvta_generic_to_shared(As);
    const uint32_t sW0 = (uint32_t)__cvta_generic_to_shared(Ws0);
    const uint32_t sW1 = (uint32_t)__cvta_generic_to_shared(Ws1);

    const int ra = tid >> 4, c16 = tid & 15;

#define LOAD_W(sdst_, chunk_)                                                   \
    _Pragma("unroll")                                                           \
    for (int i = 0; i < 8; i++) {                                               \
        int r_ = ra + i * 16;                                                   \
        cp_async16((sdst_) + (uint32_t)((r_ * ROWH + c16 * 8) * 2),             \
                   &Wt[(long)((chunk_) * 128 + r_) * 128 + c16 * 8], 16);       \
    }

#pragma unroll
    for (int i = 0; i < 8; i++) {
        int r = ra + i * 16;
        int gr = row0 + r;
        const __half* gp = &A[(long)(gr < M ? gr : 0) * 128 + c16 * 8];
        cp_async16(sA + (uint32_t)((r * ROWH + c16 * 8) * 2), gp, gr < M ? 16 : 0);
    }
    LOAD_W(sW0, 0);
    asm volatile("cp.async.commit_group;");
    LOAD_W(sW1, 1);
    asm volatile("cp.async.commit_group;");

    asm volatile("cp.async.wait_group 1;");
    __syncthreads();
    gemm_chunk(As, Ws0, C, bias, 0, M, row0, wm, wn, lq, lr);
    __syncthreads();
    LOAD_W(sW0, 2);
    asm volatile("cp.async.commit_group;");

    asm volatile("cp.async.wait_group 1;");
    __syncthreads();
    gemm_chunk(As, Ws1, C, bias, 128, M, row0, wm, wn, lq, lr);

    asm volatile("cp.async.wait_group 0;");
    __syncthreads();
    gemm_chunk(As, Ws0, C, bias, 256, M, row0, wm, wn, lq, lr);
#undef LOAD_W
}

// ---------------- GRU gates: fp16 gi/gh inputs ----------------
__global__ void gru_gates(
    const __half* __restrict__ gi, const __half* __restrict__ gh,
    float* __restrict__ h, __half* __restrict__ h16)
{
    int idx = blockIdx.x * blockDim.x + threadIdx.x;
    if (idx >= N_NODES * 32) return;
    int n = idx >> 5;
    long baseh = (long)n * D3 + (idx & 31) * 4;
    uint2 irv = *(const uint2*)&gi[baseh];
    uint2 hrv = *(const uint2*)&gh[baseh];
    uint2 izv = *(const uint2*)&gi[baseh + 128];
    uint2 hzv = *(const uint2*)&gh[baseh + 128];
    uint2 inv = *(const uint2*)&gi[baseh + 256];
    uint2 hnv = *(const uint2*)&gh[baseh + 256];
    float4 hv = ((const float4*)h)[idx];
    float ir[4], hr[4], iz[4], hz[4], in_[4], hn[4];
    {
        float2 a, b;
        a = __half22float2(*(__half2*)&irv.x); b = __half22float2(*(__half2*)&irv.y);
        ir[0]=a.x; ir[1]=a.y; ir[2]=b.x; ir[3]=b.y;
        a = __half22float2(*(__half2*)&hrv.x); b = __half22float2(*(__half2*)&hrv.y);
        hr[0]=a.x; hr[1]=a.y; hr[2]=b.x; hr[3]=b.y;
        a = __half22float2(*(__half2*)&izv.x); b = __half22float2(*(__half2*)&izv.y);
        iz[0]=a.x; iz[1]=a.y; iz[2]=b.x; iz[3]=b.y;
        a = __half22float2(*(__half2*)&hzv.x); b = __half22float2(*(__half2*)&hzv.y);
        hz[0]=a.x; hz[1]=a.y; hz[2]=b.x; hz[3]=b.y;
        a = __half22float2(*(__half2*)&inv.x); b = __half22float2(*(__half2*)&inv.y);
        in_[0]=a.x; in_[1]=a.y; in_[2]=b.x; in_[3]=b.y;
        a = __half22float2(*(__half2*)&hnv.x); b = __half22float2(*(__half2*)&hnv.y);
        hn[0]=a.x; hn[1]=a.y; hn[2]=b.x; hn[3]=b.y;
    }
    float4 ho;
#pragma unroll
    for (int q = 0; q < 4; q++) {
        float r = 1.0f / (1.0f + __expf(-(ir[q] + hr[q])));
        float z = 1.0f / (1.0f + __expf(-(iz[q] + hz[q])));
        float nn = tanh_fast(in_[q] + r * hn[q]);
        (&ho.x)[q] = (1.0f - z) * nn + z * (&hv.x)[q];
    }
    ((float4*)h)[idx] = ho;
    ((__half2*)h16)[idx * 2]     = __floats2half2_rn(ho.x, ho.y);
    ((__half2*)h16)[idx * 2 + 1] = __floats2half2_rn(ho.z, ho.w);
}

// ---------------- final linear ----------------
__global__ __launch_bounds__(256) void final_linear(
    const float* __restrict__ h, const float* __restrict__ Wl,
    const float* __restrict__ bl, float* __restrict__ out)
{
    int warp = (blockIdx.x * blockDim.x + threadIdx.x) >> 5;
    int lane = threadIdx.x & 31;
    if (warp >= N_NODES) return;
    float4 hv = ((const float4*)h)[warp * 32 + lane];
    float4 wv = ((const float4*)Wl)[lane];
    float s = hv.x * wv.x + hv.y * wv.y + hv.z * wv.z + hv.w * wv.w;
#pragma unroll
    for (int off = 16; off > 0; off >>= 1)
        s += __shfl_down_sync(0xffffffffu, s, off);
    if (lane == 0) out[warp] = s + bl[0];
}

// ---------------- launcher ----------------
extern "C" void kernel_launch(void* const* d_in, const int* in_sizes, int n_in,
                              void* d_out, int out_size)
{
    const float* x   = (const float*)d_in[0];
    const int*   ei  = (const int*)d_in[1];
    const float* Wg  = (const float*)d_in[2];
    const float* as  = (const float*)d_in[3];
    const float* ad  = (const float*)d_in[4];
    const float* bg  = (const float*)d_in[5];
    const float* Wih = (const float*)d_in[6];
    const float* Whh = (const float*)d_in[7];
    const float* bih = (const float*)d_in[8];
    const float* bhh = (const float*)d_in[9];
    const float* Wl  = (const float*)d_in[10];
    const float* bl  = (const float*)d_in[11];
    float* out = (float*)d_out;

    float *alS, *alD, *hstate;
    __half *Wg16, *Wih16, *Whh16, *hf16, *g16, *gi16, *gh16, *h16;
    int *deg, *off, *cur, *srclist;
    cudaGetSymbolAddress((void**)&alS,    d_alS);
    cudaGetSymbolAddress((void**)&alD,    d_alD);
    cudaGetSymbolAddress((void**)&hstate, d_hstate);
    cudaGetSymbolAddress((void**)&Wg16,   d_Wg16);
    cudaGetSymbolAddress((void**)&Wih16,  d_Wih16);
    cudaGetSymbolAddress((void**)&Whh16,  d_Whh16);
    cudaGetSymbolAddress((void**)&hf16,   d_hf16);
    cudaGetSymbolAddress((void**)&g16,    d_g16);
    cudaGetSymbolAddress((void**)&gi16,   d_gi16);
    cudaGetSymbolAddress((void**)&gh16,   d_gh16);
    cudaGetSymbolAddress((void**)&h16,    d_h16);
    cudaGetSymbolAddress((void**)&deg,    d_deg);
    cudaGetSymbolAddress((void**)&off,    d_off);
    cudaGetSymbolAddress((void**)&cur,    d_cur);
    cudaGetSymbolAddress((void**)&srclist, d_srclist);

    cudaFuncSetAttribute(gemm_att,
                         cudaFuncAttributeMaxDynamicSharedMemorySize, ATT_SMEM_BYTES);
    cudaFuncSetAttribute(gemm_f16_c3,
                         cudaFuncAttributeMaxDynamicSharedMemorySize, GEMM3_SMEM_BYTES);

    const int GX = (N_NODES + 127) / 128;   // 391
    const int EB = (E_EDGES + 255) / 256;

    // prologue
    zero_kernel<<<(ND + 255) / 256, 256>>>(hstate, h16, ND);
    conv_wg<<<(DDIM * F_IN + 255) / 256, 256>>>(Wg, Wg16);
    conv_w_nk<<<(D3 * DDIM + 255) / 256, 256>>>(Wih, Wih16, D3 * DDIM);
    conv_w_nk<<<(D3 * DDIM + 255) / 256, 256>>>(Whh, Whh16, D3 * DDIM);

    // ===== CSR build (all timesteps) =====
    zero_int<<<(T_STEPS * N_NODES + 255) / 256, 256>>>(deg, T_STEPS * N_NODES);
    count_kernel<<<dim3(EB, T_STEPS), 256>>>(ei, deg);
    scan_kernel<<<T_STEPS, 1024>>>(deg, off, cur);
    scatter_kernel<<<dim3(EB, T_STEPS), 256>>>(ei, cur, srclist);

    // ===== hoisted non-recurrent pipeline =====
    gemm_att<<<dim3(GX, T_STEPS), 256, ATT_SMEM_BYTES>>>(
        x, N_NODES, Wg16, hf16, as, ad, alS, alD);
    gather_kernel<<<dim3((N_NODES * 32 + 255) / 256, T_STEPS), 256>>>(
        deg, off, srclist, alS, alD, hf16, bg, g16);
    gemm_f16_c3<<<dim3(GX, 1, T_STEPS), 256, GEMM3_SMEM_BYTES>>>(
        g16, (long)ND, N_NODES, Wih16, bih, gi16, (long)N_NODES * D3);

    // ===== recurrence =====
    for (int t = 0; t < T_STEPS; t++) {
        gemm_f16_c3<<<dim3(GX, 1, 1), 256, GEMM3_SMEM_BYTES>>>(
            h16, 0L, N_NODES, Whh16, bhh, gh16, 0L);
        gru_gates<<<(N_NODES * 32 + 255) / 256, 256>>>(
            gi16 + (long)t * N_NODES * D3, gh16, hstate, h16);
    }

    final_linear<<<(N_NODES * 32 + 255) / 256, 256>>>(hstate, Wl, bl, out);
}